// round 10
// baseline (speedup 1.0000x reference)
#include <cuda_runtime.h>
#include <stdint.h>
#include <math.h>

#define BATCH 512
#define OUTF  1024
#define KPOS  256
#define NIDX  4096
#define BTILE 8
#define BG    64          // batch groups (8 batches each)
#define KQ    4           // k quarters
#define KQLEN 64          // k's per CTA
#define SLOT  32768       // NIDX * BTILE bytes per buffer slot
#define SMEM_SZ (2 * SLOT + KQLEN * BTILE * 2)   // 66560 B

// ---- device scratch (no allocations allowed) ----
__device__ uint8_t  g_tab[NIDX * NIDX];           // 16MB compact u8 table
__device__ ushort4  g_w4[(KPOS / 4) * OUTF];      // PRE-SWIZZLED 8B offsets [kb][o]
__device__ uint4    g_part[BG * OUTF * KQ];       // partials: 4MB
__device__ int      g_mode;                       // 0=u8, 1=int32, 2=float32

// -------- detect how the table was uploaded (vectorized) --------
__global__ void detect_kernel(const uint4* __restrict__ w) {
    int lane = threadIdx.x;
    bool small = true, isf = true;
#pragma unroll
    for (int i = 0; i < 8; i++) {
        uint4 x4 = w[lane + i * 32];
        uint32_t xs[4] = {x4.x, x4.y, x4.z, x4.w};
#pragma unroll
        for (int j = 0; j < 4; j++) {
            uint32_t x = xs[j];
            small = small && (x < 256u);
            float f = __uint_as_float(x);
            isf = isf && (f >= 0.0f) && (f < 256.0f) && (f == truncf(f));
        }
    }
    small = __all_sync(0xFFFFFFFFu, small);
    isf   = __all_sync(0xFFFFFFFFu, isf);
    if (lane == 0) g_mode = small ? 1 : (isf ? 2 : 0);
}

// -------- compact table -> u8 (16 bytes per thread) --------
__global__ void convert_kernel(const void* __restrict__ table) {
    const int mode = g_mode;
    const int t = blockIdx.x * blockDim.x + threadIdx.x;  // 1M threads
    uint4 o;
    if (mode == 1) {
        const int4* src = (const int4*)table;
        uint32_t p[4];
#pragma unroll
        for (int s = 0; s < 4; s++) {
            int4 v = src[t * 4 + s];
            p[s] = (uint32_t)(v.x & 255) | ((uint32_t)(v.y & 255) << 8) |
                   ((uint32_t)(v.z & 255) << 16) | ((uint32_t)(v.w & 255) << 24);
        }
        o = make_uint4(p[0], p[1], p[2], p[3]);
    } else if (mode == 2) {
        const float4* src = (const float4*)table;
        uint32_t p[4];
#pragma unroll
        for (int s = 0; s < 4; s++) {
            float4 v = src[t * 4 + s];
            p[s] = (uint32_t)v.x | ((uint32_t)v.y << 8) |
                   ((uint32_t)v.z << 16) | ((uint32_t)v.w << 24);
        }
        o = make_uint4(p[0], p[1], p[2], p[3]);
    } else {
        o = ((const uint4*)table)[t];
    }
    *(uint4*)&g_tab[t * 16] = o;
}

// swizzle: XOR bits[4:6] with bits[7:9]; bijective, preserves 8B alignment
__device__ __forceinline__ uint32_t sw3(uint32_t a) {
    return a ^ ((a >> 3) & 0x70u);
}

// -------- pre-pass: clamp, *8, PRE-SWIZZLE, pack as ushort4 per 4-k block ----
__global__ void prep_w_kernel(const int* __restrict__ w_idx) {
    int t = blockIdx.x * blockDim.x + threadIdx.x;   // 64 * 1024
    int kb = t >> 10;
    int o  = t & 1023;
    int4 v = *(const int4*)&w_idx[o * KPOS + kb * 4];
    uint32_t a = (uint32_t)(v.x < 0 ? 0 : (v.x > NIDX - 1 ? NIDX - 1 : v.x)) * 8u;
    uint32_t b = (uint32_t)(v.y < 0 ? 0 : (v.y > NIDX - 1 ? NIDX - 1 : v.y)) * 8u;
    uint32_t c = (uint32_t)(v.z < 0 ? 0 : (v.z > NIDX - 1 ? NIDX - 1 : v.z)) * 8u;
    uint32_t d = (uint32_t)(v.w < 0 ? 0 : (v.w > NIDX - 1 ? NIDX - 1 : v.w)) * 8u;
    g_w4[t] = make_ushort4((uint16_t)sw3(a), (uint16_t)sw3(b),
                           (uint16_t)sw3(c), (uint16_t)sw3(d));
}

// 8x8-byte transpose of q (8 rows x 8B) -> interleaved entries buf[w*8+j],
// stored as 4 STS.128 at precomputed swizzled addresses.
__device__ __forceinline__ void transpose_store8(uint8_t* bufp, const uint32_t* sa,
                                                 const uint2* q) {
    uint32_t l0 = q[0].x, l1 = q[1].x, l2 = q[2].x, l3 = q[3].x;
    uint32_t m0 = q[4].x, m1 = q[5].x, m2 = q[6].x, m3 = q[7].x;
    // cols 0-1
    uint32_t x0 = __byte_perm(l0, l1, 0x5140), x1 = __byte_perm(l2, l3, 0x5140);
    uint32_t u0 = __byte_perm(m0, m1, 0x5140), u1 = __byte_perm(m2, m3, 0x5140);
    uint4 s0;
    s0.x = __byte_perm(x0, x1, 0x5410);  // A0
    s0.y = __byte_perm(u0, u1, 0x5410);  // B0
    s0.z = __byte_perm(x0, x1, 0x7632);  // A1
    s0.w = __byte_perm(u0, u1, 0x7632);  // B1
    *(uint4*)(bufp + sa[0]) = s0;
    // cols 2-3
    uint32_t y0 = __byte_perm(l0, l1, 0x7362), y1 = __byte_perm(l2, l3, 0x7362);
    uint32_t v0 = __byte_perm(m0, m1, 0x7362), v1 = __byte_perm(m2, m3, 0x7362);
    uint4 s1;
    s1.x = __byte_perm(y0, y1, 0x5410);
    s1.y = __byte_perm(v0, v1, 0x5410);
    s1.z = __byte_perm(y0, y1, 0x7632);
    s1.w = __byte_perm(v0, v1, 0x7632);
    *(uint4*)(bufp + sa[1]) = s1;
    uint32_t h0 = q[0].y, h1 = q[1].y, h2 = q[2].y, h3 = q[3].y;
    uint32_t n0 = q[4].y, n1 = q[5].y, n2 = q[6].y, n3 = q[7].y;
    // cols 4-5
    x0 = __byte_perm(h0, h1, 0x5140); x1 = __byte_perm(h2, h3, 0x5140);
    u0 = __byte_perm(n0, n1, 0x5140); u1 = __byte_perm(n2, n3, 0x5140);
    uint4 s2;
    s2.x = __byte_perm(x0, x1, 0x5410);
    s2.y = __byte_perm(u0, u1, 0x5410);
    s2.z = __byte_perm(x0, x1, 0x7632);
    s2.w = __byte_perm(u0, u1, 0x7632);
    *(uint4*)(bufp + sa[2]) = s2;
    // cols 6-7
    y0 = __byte_perm(h0, h1, 0x7362); y1 = __byte_perm(h2, h3, 0x7362);
    v0 = __byte_perm(n0, n1, 0x7362); v1 = __byte_perm(n2, n3, 0x7362);
    uint4 s3;
    s3.x = __byte_perm(y0, y1, 0x5410);
    s3.y = __byte_perm(v0, v1, 0x5410);
    s3.z = __byte_perm(y0, y1, 0x7632);
    s3.w = __byte_perm(v0, v1, 0x7632);
    *(uint4*)(bufp + sa[3]) = s3;
}

// -------- main kernel --------
// CTA = 512 thr, 8 batches x 1024 outputs (2/thread) x quarter of the k's.
// All threads stage every k (8B from each of 8 rows, distance-1 preload in q),
// gather is one LDS.64 per (o,k) serving all 8 batches. 1 barrier per k.
__global__ __launch_bounds__(512, 2)
void lookup_kernel(const int* __restrict__ in_idx) {
    extern __shared__ __align__(16) uint8_t smem[];
    uint16_t* iid = (uint16_t*)(smem + 2 * SLOT);   // [KQLEN][8] u16 indices

    const int tid = threadIdx.x;
    const int bg  = blockIdx.x >> 2;
    const int kq  = blockIdx.x & 3;
    const int b0  = bg * BTILE;
    const int k0  = kq * KQLEN;

    // stage this quarter's input indices as u16 [k][j] (clamped)
    {
        int k = tid & 63, j = tid >> 6;
        int v = in_idx[(b0 + j) * KPOS + k0 + k];
        v = v < 0 ? 0 : (v > NIDX - 1 ? NIDX - 1 : v);
        iid[k * 8 + j] = (uint16_t)v;
    }

    // precomputed swizzled store addresses (this thread owns cols 8c..8c+7)
    const uint32_t c = (uint32_t)tid;
    uint32_t sa[4];
#pragma unroll
    for (int s = 0; s < 4; s++) sa[s] = sw3(64u * c + 16u * s);

    __syncthreads();

    // ---- prologue: load + store k=0 into slot 0 ----
    uint2 q[8];
    {
        uint4 iv = *(const uint4*)&iid[0];
        uint32_t r[8] = {iv.x & 0xFFFFu, iv.x >> 16, iv.y & 0xFFFFu, iv.y >> 16,
                         iv.z & 0xFFFFu, iv.z >> 16, iv.w & 0xFFFFu, iv.w >> 16};
#pragma unroll
        for (int j = 0; j < 8; j++)
            q[j] = *(const uint2*)(g_tab + (size_t)r[j] * 4096 + 8u * c);
        transpose_store8(smem, sa, q);
    }
    __syncthreads();

    uint32_t P0 = 0, P1 = 0, P2 = 0, P3 = 0;  // o = tid   : pairs (b0,b1)(b2,b3)(b4,b5)(b6,b7)
    uint32_t Q0 = 0, Q1 = 0, Q2 = 0, Q3 = 0;  // o = tid+512

    for (int kb = 0; kb < KQLEN / 4; kb++) {
        const int gkb = kq * (KQLEN / 4) + kb;
        ushort4 w4a = g_w4[gkb * OUTF + tid];          // pre-swizzled 8B offsets
        ushort4 w4b = g_w4[gkb * OUTF + tid + 512];
        uint16_t wa[4] = {w4a.x, w4a.y, w4a.z, w4a.w};
        uint16_t wb[4] = {w4b.x, w4b.y, w4b.z, w4b.w};
#pragma unroll
        for (int u = 0; u < 4; u++) {
            const int k = kb * 4 + u;
            // preload k+1's 8 rows (one broadcast LDS.128 for the indices)
            if (k + 1 < KQLEN) {
                uint4 iv = *(const uint4*)&iid[(k + 1) * 8];
                uint32_t r[8] = {iv.x & 0xFFFFu, iv.x >> 16, iv.y & 0xFFFFu, iv.y >> 16,
                                 iv.z & 0xFFFFu, iv.z >> 16, iv.w & 0xFFFFu, iv.w >> 16};
#pragma unroll
                for (int j = 0; j < 8; j++)
                    q[j] = *(const uint2*)(g_tab + (size_t)r[j] * 4096 + 8u * c);
            }
            // gather k: one LDS.64 per output serves all 8 batches
            const uint8_t* bp = smem + (k & 1) * SLOT;
            uint2 va = *(const uint2*)(bp + wa[u]);
            uint2 vb = *(const uint2*)(bp + wb[u]);
            P0 = __vadd2(P0, __byte_perm(va.x, 0, 0x4140));
            P1 = __vadd2(P1, __byte_perm(va.x, 0, 0x4342));
            P2 = __vadd2(P2, __byte_perm(va.y, 0, 0x4140));
            P3 = __vadd2(P3, __byte_perm(va.y, 0, 0x4342));
            Q0 = __vadd2(Q0, __byte_perm(vb.x, 0, 0x4140));
            Q1 = __vadd2(Q1, __byte_perm(vb.x, 0, 0x4342));
            Q2 = __vadd2(Q2, __byte_perm(vb.y, 0, 0x4140));
            Q3 = __vadd2(Q3, __byte_perm(vb.y, 0, 0x4342));
            // store k+1 into the other slot
            if (k + 1 < KQLEN)
                transpose_store8(smem + ((k + 1) & 1) * SLOT, sa, q);
            __syncthreads();
        }
    }

    // ---- write packed u16 partials (one uint4 per (o, kq); no atomics) ----
    g_part[(uint32_t)(bg * OUTF + tid) * 4u + kq]       = make_uint4(P0, P1, P2, P3);
    g_part[(uint32_t)(bg * OUTF + tid + 512) * 4u + kq] = make_uint4(Q0, Q1, Q2, Q3);
}

// -------- reduce: sum 4 k-quarters, dequantize, write 8 batch outputs --------
__global__ __launch_bounds__(256)
void reduce_kernel(const float* __restrict__ scale_p,
                   const float* __restrict__ zp_p,
                   float* __restrict__ out) {
    int t  = blockIdx.x * blockDim.x + threadIdx.x;   // 64*1024 threads
    int bg = t >> 10;
    int o  = t & 1023;
    const uint4* pp = &g_part[(uint32_t)(bg * OUTF + o) * 4u];
    uint4 p0 = pp[0], p1 = pp[1], p2 = pp[2], p3 = pp[3];
    uint32_t S0 = __vadd2(__vadd2(p0.x, p1.x), __vadd2(p2.x, p3.x));
    uint32_t S1 = __vadd2(__vadd2(p0.y, p1.y), __vadd2(p2.y, p3.y));
    uint32_t S2 = __vadd2(__vadd2(p0.z, p1.z), __vadd2(p2.z, p3.z));
    uint32_t S3 = __vadd2(__vadd2(p0.w, p1.w), __vadd2(p2.w, p3.w));
    const float scale = *scale_p;
    const float zp    = *zp_p;
    const float bias  = 256.0f * zp;
    int b0 = bg * BTILE;
    out[(b0 + 0) * OUTF + o] = ((float)(S0 & 0xFFFFu) - bias) * scale;
    out[(b0 + 1) * OUTF + o] = ((float)(S0 >> 16)     - bias) * scale;
    out[(b0 + 2) * OUTF + o] = ((float)(S1 & 0xFFFFu) - bias) * scale;
    out[(b0 + 3) * OUTF + o] = ((float)(S1 >> 16)     - bias) * scale;
    out[(b0 + 4) * OUTF + o] = ((float)(S2 & 0xFFFFu) - bias) * scale;
    out[(b0 + 5) * OUTF + o] = ((float)(S2 >> 16)     - bias) * scale;
    out[(b0 + 6) * OUTF + o] = ((float)(S3 & 0xFFFFu) - bias) * scale;
    out[(b0 + 7) * OUTF + o] = ((float)(S3 >> 16)     - bias) * scale;
}

extern "C" void kernel_launch(void* const* d_in, const int* in_sizes, int n_in,
                              void* d_out, int out_size) {
    (void)in_sizes; (void)n_in; (void)out_size;
    const int*   in_idx = (const int*)d_in[0];
    const int*   w_idx  = (const int*)d_in[1];
    const void*  table  = (const void*)d_in[2];
    const float* scale  = (const float*)d_in[3];
    const float* zp     = (const float*)d_in[4];
    float*       outp   = (float*)d_out;

    // Not stream-ordered; safe on every call (incl. during graph capture).
    cudaFuncSetAttribute(lookup_kernel,
                         cudaFuncAttributeMaxDynamicSharedMemorySize, SMEM_SZ);

    detect_kernel<<<1, 32>>>((const uint4*)table);
    convert_kernel<<<(NIDX * NIDX / 16) / 256, 256>>>(table);
    prep_w_kernel<<<(OUTF * KPOS / 4) / 256, 256>>>(w_idx);
    lookup_kernel<<<BG * KQ, 512, SMEM_SZ>>>(in_idx);
    reduce_kernel<<<(BG * OUTF) / 256, 256>>>(scale, zp, outp);
}

// round 11
// speedup vs baseline: 1.0388x; 1.0388x over previous
#include <cuda_runtime.h>
#include <stdint.h>
#include <math.h>

#define BATCH 512
#define OUTF  1024
#define KPOS  256
#define KHALF 128
#define NIDX  4096
#define BTILE 4
#define SLOT  16384                               // NIDX * BTILE
#define SMEM_SZ (4 * SLOT + KHALF * 8)            // 66560 B

// ---- device scratch (no allocations allowed) ----
__device__ uint8_t  g_tab[NIDX * NIDX];           // 16MB compact u8 table
__device__ ushort4  g_w4[(KPOS / 4) * OUTF];      // PRE-SWIZZLED 4B offsets [kb][o]
__device__ uint4    g_part[128 * OUTF];           // partials per (bg,o): 2MB
__device__ int      g_mode;                       // 0=u8, 1=int32, 2=float32

// -------- detect how the table was uploaded (vectorized) --------
__global__ void detect_kernel(const uint4* __restrict__ w) {
    int lane = threadIdx.x;
    bool small = true, isf = true;
#pragma unroll
    for (int i = 0; i < 8; i++) {
        uint4 x4 = w[lane + i * 32];
        uint32_t xs[4] = {x4.x, x4.y, x4.z, x4.w};
#pragma unroll
        for (int j = 0; j < 4; j++) {
            uint32_t x = xs[j];
            small = small && (x < 256u);
            float f = __uint_as_float(x);
            isf = isf && (f >= 0.0f) && (f < 256.0f) && (f == truncf(f));
        }
    }
    small = __all_sync(0xFFFFFFFFu, small);
    isf   = __all_sync(0xFFFFFFFFu, isf);
    if (lane == 0) g_mode = small ? 1 : (isf ? 2 : 0);
}

// -------- compact table -> u8 (16 bytes per thread) --------
__global__ void convert_kernel(const void* __restrict__ table) {
    const int mode = g_mode;
    const int t = blockIdx.x * blockDim.x + threadIdx.x;  // 1M threads
    uint4 o;
    if (mode == 1) {
        const int4* src = (const int4*)table;
        uint32_t p[4];
#pragma unroll
        for (int s = 0; s < 4; s++) {
            int4 v = src[t * 4 + s];
            p[s] = (uint32_t)(v.x & 255) | ((uint32_t)(v.y & 255) << 8) |
                   ((uint32_t)(v.z & 255) << 16) | ((uint32_t)(v.w & 255) << 24);
        }
        o = make_uint4(p[0], p[1], p[2], p[3]);
    } else if (mode == 2) {
        const float4* src = (const float4*)table;
        uint32_t p[4];
#pragma unroll
        for (int s = 0; s < 4; s++) {
            float4 v = src[t * 4 + s];
            p[s] = (uint32_t)v.x | ((uint32_t)v.y << 8) |
                   ((uint32_t)v.z << 16) | ((uint32_t)v.w << 24);
        }
        o = make_uint4(p[0], p[1], p[2], p[3]);
    } else {
        o = ((const uint4*)table)[t];
    }
    *(uint4*)&g_tab[t * 16] = o;
}

// swizzle: XOR bits[4:5] with bits[7:8]; bijective within a 16KB slot
__device__ __forceinline__ uint32_t sw(uint32_t a) {
    return a ^ ((a >> 3) & 0x30u);
}

// -------- pre-pass: clamp, *4, PRE-SWIZZLE, pack as ushort4 per 4-k block ----
__global__ void prep_w_kernel(const int* __restrict__ w_idx) {
    int t = blockIdx.x * blockDim.x + threadIdx.x;   // 64 * 1024
    int kb = t >> 10;
    int o  = t & 1023;
    int4 v = *(const int4*)&w_idx[o * KPOS + kb * 4];
    uint32_t a = (uint32_t)(v.x < 0 ? 0 : (v.x > NIDX - 1 ? NIDX - 1 : v.x)) * 4u;
    uint32_t b = (uint32_t)(v.y < 0 ? 0 : (v.y > NIDX - 1 ? NIDX - 1 : v.y)) * 4u;
    uint32_t c = (uint32_t)(v.z < 0 ? 0 : (v.z > NIDX - 1 ? NIDX - 1 : v.z)) * 4u;
    uint32_t d = (uint32_t)(v.w < 0 ? 0 : (v.w > NIDX - 1 ? NIDX - 1 : v.w)) * 4u;
    g_w4[t] = make_ushort4((uint16_t)sw(a), (uint16_t)sw(b),
                           (uint16_t)sw(c), (uint16_t)sw(d));
}

// transpose 4 rows x 16B -> interleaved entries buf[w*4+j] (swizzled addrs)
__device__ __forceinline__ void transpose_store(uint8_t* bufp, const uint32_t* sa,
                                                const uint4* q) {
#pragma unroll
    for (int s = 0; s < 4; s++) {
        uint32_t r0 = ((const uint32_t*)&q[0])[s];
        uint32_t r1 = ((const uint32_t*)&q[1])[s];
        uint32_t r2 = ((const uint32_t*)&q[2])[s];
        uint32_t r3 = ((const uint32_t*)&q[3])[s];
        uint32_t t0 = __byte_perm(r0, r1, 0x5140);
        uint32_t t1 = __byte_perm(r0, r1, 0x7362);
        uint32_t t2 = __byte_perm(r2, r3, 0x5140);
        uint32_t t3 = __byte_perm(r2, r3, 0x7362);
        uint4 o4;
        o4.x = __byte_perm(t0, t2, 0x5410);
        o4.y = __byte_perm(t0, t2, 0x7632);
        o4.z = __byte_perm(t1, t3, 0x5410);
        o4.w = __byte_perm(t1, t3, 0x7632);
        *(uint4*)(bufp + sa[s]) = o4;
    }
}

// -------- main kernel --------
// CTA = 512 thr, 4 batches x 1024 outputs (2/thread) x half the k's; 2 CTAs/SM.
// 4-slot ring, barrier every 2 k's. Interval t: gather k=2t,2t+1; group g
// stores k=2t+2+g (preloaded a full interval earlier) and preloads k=2t+4+g.
// All warps do identical work each interval (1 store + 1 preload + 2 gathers).
__global__ __launch_bounds__(512, 2)
void lookup_kernel(const int* __restrict__ in_idx) {
    extern __shared__ __align__(16) uint8_t smem[];
    ushort4* iid = (ushort4*)(smem + 4 * SLOT);   // [KHALF] packed row indices

    const int tid = threadIdx.x;
    const int wg  = tid >> 8;          // warp-group 0..1
    const int l   = tid & 255;         // 16B chunk within row
    const int bg  = blockIdx.x >> 1;
    const int kh  = blockIdx.x & 1;
    const int b0  = bg * BTILE;
    const uint4* tab128 = (const uint4*)g_tab;

    // stage this half's input indices as packed u16 (clamped):
    // thread t = j*128 + k writes field j of iid[k]
    {
        int j = tid >> 7, kk = tid & 127;
        int v = in_idx[(b0 + j) * KPOS + kh * KHALF + kk];
        v = v < 0 ? 0 : (v > NIDX - 1 ? NIDX - 1 : v);
        *((uint16_t*)&iid[kk] + j) = (uint16_t)v;
    }

    // precomputed swizzled store addresses
    uint32_t sa[4];
#pragma unroll
    for (int s = 0; s < 4; s++) sa[s] = sw(64u * (uint32_t)l + 16u * s);

    __syncthreads();

    // ---- prologue: group g stores k=g into slot g, preloads k=2+g ----
    uint4 q[4];
    {
        ushort4 iv = iid[wg];
        uint32_t r[4] = {iv.x, iv.y, iv.z, iv.w};
#pragma unroll
        for (int j = 0; j < 4; j++)
            q[j] = tab128[r[j] * 256 + l];
        transpose_store(smem + wg * SLOT, sa, q);
        ushort4 iv2 = iid[2 + wg];
        uint32_t r2[4] = {iv2.x, iv2.y, iv2.z, iv2.w};
#pragma unroll
        for (int j = 0; j < 4; j++)
            q[j] = tab128[r2[j] * 256 + l];
    }
    __syncthreads();

    uint32_t accLo0 = 0, accHi0 = 0;   // output o = tid
    uint32_t accLo1 = 0, accHi1 = 0;   // output o = tid + 512

    for (int kb = 0; kb < KHALF / 4; kb++) {
        const int gkb = kh * (KHALF / 4) + kb;
        ushort4 w4a = g_w4[gkb * OUTF + tid];          // pre-swizzled offsets
        ushort4 w4b = g_w4[gkb * OUTF + tid + 512];
        uint16_t wa[4] = {w4a.x, w4a.y, w4a.z, w4a.w};
        uint16_t wb[4] = {w4b.x, w4b.y, w4b.z, w4b.w};
#pragma unroll
        for (int h = 0; h < 2; h++) {
            const int k  = kb * 4 + h * 2;     // interval covers k, k+1
            const int ks = k + 2 + wg;         // my store target
            // store preloaded ks (slot disjoint from gathered slots)
            if (ks < KHALF)
                transpose_store(smem + (ks & 3) * SLOT, sa, q);
            // issue preload of ks+2 (consumed next interval)
            if (ks + 2 < KHALF) {
                ushort4 iv = iid[ks + 2];
                uint32_t r[4] = {iv.x, iv.y, iv.z, iv.w};
#pragma unroll
                for (int j = 0; j < 4; j++)
                    q[j] = tab128[r[j] * 256 + l];
            }
            // gather k and k+1 for both outputs
            const uint8_t* bp0 = smem + (k & 3) * SLOT;
            const uint8_t* bp1 = smem + ((k + 1) & 3) * SLOT;
            uint32_t va0 = *(const uint32_t*)(bp0 + wa[h * 2]);
            uint32_t vb0 = *(const uint32_t*)(bp0 + wb[h * 2]);
            uint32_t va1 = *(const uint32_t*)(bp1 + wa[h * 2 + 1]);
            uint32_t vb1 = *(const uint32_t*)(bp1 + wb[h * 2 + 1]);
            accLo0 = __vadd2(accLo0, __byte_perm(va0, 0, 0x4140));
            accHi0 = __vadd2(accHi0, __byte_perm(va0, 0, 0x4342));
            accLo1 = __vadd2(accLo1, __byte_perm(vb0, 0, 0x4140));
            accHi1 = __vadd2(accHi1, __byte_perm(vb0, 0, 0x4342));
            accLo0 = __vadd2(accLo0, __byte_perm(va1, 0, 0x4140));
            accHi0 = __vadd2(accHi0, __byte_perm(va1, 0, 0x4342));
            accLo1 = __vadd2(accLo1, __byte_perm(vb1, 0, 0x4140));
            accHi1 = __vadd2(accHi1, __byte_perm(vb1, 0, 0x4342));
            __syncthreads();
        }
    }

    // ---- write packed u16 partials (disjoint 8B halves per kh; no atomics) ----
    uint32_t* gp = (uint32_t*)g_part;
    uint32_t base0 = (uint32_t)(bg * OUTF + tid) * 4u + (uint32_t)kh * 2u;
    uint32_t base1 = (uint32_t)(bg * OUTF + tid + 512) * 4u + (uint32_t)kh * 2u;
    gp[base0]     = accLo0;
    gp[base0 + 1] = accHi0;
    gp[base1]     = accLo1;
    gp[base1 + 1] = accHi1;
}

// -------- reduce: combine k-halves, dequantize, write out --------
__global__ __launch_bounds__(256)
void reduce_kernel(const float* __restrict__ scale_p,
                   const float* __restrict__ zp_p,
                   float* __restrict__ out) {
    int t  = blockIdx.x * blockDim.x + threadIdx.x;   // 128*1024
    int bg = t >> 10;
    int o  = t & 1023;
    uint4 p = g_part[bg * OUTF + o];                  // one LDG.128
    uint32_t Lo = __vadd2(p.x, p.z);   // u16 sums <= 65280, no overflow
    uint32_t Hi = __vadd2(p.y, p.w);
    const float scale = *scale_p;
    const float zp    = *zp_p;
    const float bias  = 256.0f * zp;
    int b0 = bg * BTILE;
    out[(b0 + 0) * OUTF + o] = ((float)(Lo & 0xFFFFu) - bias) * scale;
    out[(b0 + 1) * OUTF + o] = ((float)(Lo >> 16)     - bias) * scale;
    out[(b0 + 2) * OUTF + o] = ((float)(Hi & 0xFFFFu) - bias) * scale;
    out[(b0 + 3) * OUTF + o] = ((float)(Hi >> 16)     - bias) * scale;
}

extern "C" void kernel_launch(void* const* d_in, const int* in_sizes, int n_in,
                              void* d_out, int out_size) {
    (void)in_sizes; (void)n_in; (void)out_size;
    const int*   in_idx = (const int*)d_in[0];
    const int*   w_idx  = (const int*)d_in[1];
    const void*  table  = (const void*)d_in[2];
    const float* scale  = (const float*)d_in[3];
    const float* zp     = (const float*)d_in[4];
    float*       outp   = (float*)d_out;

    // Not stream-ordered; safe on every call (incl. during graph capture).
    cudaFuncSetAttribute(lookup_kernel,
                         cudaFuncAttributeMaxDynamicSharedMemorySize, SMEM_SZ);

    detect_kernel<<<1, 32>>>((const uint4*)table);
    convert_kernel<<<(NIDX * NIDX / 16) / 256, 256>>>(table);
    prep_w_kernel<<<(OUTF * KPOS / 4) / 256, 256>>>(w_idx);
    lookup_kernel<<<2 * (BATCH / BTILE), 512, SMEM_SZ>>>(in_idx);
    reduce_kernel<<<(128 * OUTF) / 256, 256>>>(scale, zp, outp);
}